// round 2
// baseline (speedup 1.0000x reference)
#include <cuda_runtime.h>

#define BN_EPS 1e-5f

// ---------------------------------------------------------------------------
// Scratch (device globals -- no allocation allowed)
// ---------------------------------------------------------------------------
__device__ float g_x1[16 * 512 * 64 * 64];   // conv1 output (16,512,64,64)
__device__ float g_pooled[16 * 512 * 16];    // pooled (16,512,4,4)

// ---------------------------------------------------------------------------
// Fused conv3x3(SAME) + BN + ReLU  [+ 16x16 avg-pool when POOL]
// Block: 256 threads. Output tile: 64 oc x (16x16 spatial) for one batch img.
// Thread tile: 8 oc x 8 spatial (one row segment of 8 contiguous cols).
// Grid: (16 spatial tiles, C_OUT/64 = 8, B = 16)
// ---------------------------------------------------------------------------
template <int CIN, bool POOL>
__global__ __launch_bounds__(256, 2)
void conv_bn_relu_kernel(const float* __restrict__ in,
                         const float* __restrict__ w,
                         const float* __restrict__ bias,
                         const float* __restrict__ bng,
                         const float* __restrict__ bnb,
                         const float* __restrict__ bnm,
                         const float* __restrict__ bnv,
                         float* __restrict__ out)
{
    __shared__ float s_in[8 * 18 * 18];   // [c][r][col], row stride 18
    __shared__ float s_w[64 * 72];        // [oc][c*9+tap]

    const int tile   = blockIdx.x;            // 0..15
    const int ty     = tile >> 2;
    const int tx     = tile & 3;
    const int base_h = ty * 16;
    const int base_w = tx * 16;
    const int oc0    = blockIdx.y * 64;
    const int b      = blockIdx.z;

    const int tid  = threadIdx.x;
    const int oc_g = tid >> 5;                // warp id (0..7): one oc-octet per warp
    const int sp_g = tid & 31;                // lane: spatial group
    const int r    = sp_g >> 1;               // row in tile (0..15)
    const int cb   = (sp_g & 1) * 8;          // col base (0 or 8)

    float acc[64];
#pragma unroll
    for (int i = 0; i < 64; i++) acc[i] = 0.f;

    const float* in_b = in + (long long)b * CIN * 64 * 64;

    for (int c0 = 0; c0 < CIN; c0 += 8) {
        __syncthreads();
        // ---- load input chunk (8 cin x 18x18 with halo, zero-padded) ----
        for (int idx = tid; idx < 8 * 18 * 18; idx += 256) {
            int c   = idx / 324;
            int rem = idx - c * 324;
            int rr  = rem / 18;
            int cc  = rem - rr * 18;
            int hi  = base_h - 1 + rr;
            int wi  = base_w - 1 + cc;
            float val = 0.f;
            if (hi >= 0 && hi < 64 && wi >= 0 && wi < 64)
                val = in_b[((long long)(c0 + c) * 64 + hi) * 64 + wi];
            s_in[idx] = val;
        }
        // ---- load weights (coalesced LDG, conflict-free STS) ----
        for (int idx = tid; idx < 64 * 72; idx += 256) {
            int oc = idx / 72;
            int t  = idx - oc * 72;   // t = c*9 + tap
            s_w[idx] = w[((long long)(oc0 + oc) * CIN + c0) * 9 + t];
        }
        __syncthreads();

        // ---- main FMA loop: 8 cin x 9 taps; 64 FMA per 16 LDS ----
        for (int c = 0; c < 8; ++c) {
#pragma unroll
            for (int ky = 0; ky < 3; ++ky) {
#pragma unroll
                for (int kx = 0; kx < 3; ++kx) {
                    float in8[8];
#pragma unroll
                    for (int i = 0; i < 8; i++)
                        in8[i] = s_in[c * 324 + (r + ky) * 18 + cb + kx + i];
                    float w8[8];
#pragma unroll
                    for (int j = 0; j < 8; j++)
                        w8[j] = s_w[(oc_g * 8 + j) * 72 + c * 9 + ky * 3 + kx];
#pragma unroll
                    for (int j = 0; j < 8; j++)
#pragma unroll
                        for (int i = 0; i < 8; i++)
                            acc[j * 8 + i] = fmaf(in8[i], w8[j], acc[j * 8 + i]);
                }
            }
        }
    }

    // ---- epilogue: BN + ReLU (+ pool) ----
    if (!POOL) {
#pragma unroll
        for (int j = 0; j < 8; j++) {
            int oc = oc0 + oc_g * 8 + j;
            float s = bng[oc] * rsqrtf(bnv[oc] + BN_EPS);
            float t = bnb[oc] + (bias[oc] - bnm[oc]) * s;
            float vv[8];
#pragma unroll
            for (int i = 0; i < 8; i++)
                vv[i] = fmaxf(fmaf(acc[j * 8 + i], s, t), 0.f);
            float* op = out + (((long long)b * 512 + oc) * 64 + base_h + r) * 64
                            + base_w + cb;
            *(float4*)op       = make_float4(vv[0], vv[1], vv[2], vv[3]);
            *(float4*)(op + 4) = make_float4(vv[4], vv[5], vv[6], vv[7]);
        }
    } else {
        // tile == one 16x16 pool window: reduce within thread, then across warp
        float ps[8];
#pragma unroll
        for (int j = 0; j < 8; j++) {
            int oc = oc0 + oc_g * 8 + j;
            float s = bng[oc] * rsqrtf(bnv[oc] + BN_EPS);
            float t = bnb[oc] + (bias[oc] - bnm[oc]) * s;
            float sum = 0.f;
#pragma unroll
            for (int i = 0; i < 8; i++)
                sum += fmaxf(fmaf(acc[j * 8 + i], s, t), 0.f);
            ps[j] = sum;
        }
#pragma unroll
        for (int j = 0; j < 8; j++) {
#pragma unroll
            for (int off = 16; off; off >>= 1)
                ps[j] += __shfl_down_sync(0xffffffffu, ps[j], off);
        }
        if (sp_g == 0) {
#pragma unroll
            for (int j = 0; j < 8; j++) {
                int oc = oc0 + oc_g * 8 + j;
                out[(((long long)b * 512 + oc) * 4 + ty) * 4 + tx] =
                    ps[j] * (1.f / 256.f);
            }
        }
    }
}

// ---------------------------------------------------------------------------
// Tail: clin embed + concat + (ph1,ph2,ph3 sigmoid) + (ls1,ls2) + sampling.
// One block per batch element, 256 threads (8 warps, warp-per-output GEMV).
// ---------------------------------------------------------------------------
__global__ __launch_bounds__(256)
void tail_kernel(const float* __restrict__ clinical,
                 const float* __restrict__ noise,   // (16,3,4)
                 const float* __restrict__ u,       // (16,3,5,2)
                 const float* __restrict__ clin_w, const float* __restrict__ clin_b,
                 const float* __restrict__ ph1_w,  const float* __restrict__ ph1_b,
                 const float* __restrict__ ph2_w,  const float* __restrict__ ph2_b,
                 const float* __restrict__ ph3_w,  const float* __restrict__ ph3_b,
                 const float* __restrict__ ls1_w,  const float* __restrict__ ls1_b,
                 const float* __restrict__ ls2_w,  const float* __restrict__ ls2_b,
                 float* __restrict__ out, int out_size)
{
    __shared__ float pv[8320];
    __shared__ float h1[512];
    __shared__ float h2[256];
    __shared__ float g1v[256];
    __shared__ float s_pm[12];
    __shared__ float s_ls[12];
    __shared__ float s_fin[12];

    const int b    = blockIdx.x;
    const int tid  = threadIdx.x;
    const int warp = tid >> 5;
    const int lane = tid & 31;

    // pooled features + clinical embedding -> pv[8320]
    for (int i = tid; i < 8192; i += 256) pv[i] = g_pooled[b * 8192 + i];
    if (tid < 128) {
        float a = clin_b[tid];
#pragma unroll
        for (int j = 0; j < 4; j++) a += clin_w[tid * 4 + j] * clinical[b * 4 + j];
        pv[8192 + tid] = a;
    }
    __syncthreads();

    // h1 = relu(ph1_w @ pv + b)   (512 x 8320) -- warp per output
    for (int oo = warp; oo < 512; oo += 8) {
        float a = 0.f;
        const float* wr = ph1_w + (long long)oo * 8320;
#pragma unroll 4
        for (int jb = 0; jb < 65; ++jb) {
            int j0 = jb * 128 + lane * 4;
            float4 wv = *(const float4*)&wr[j0];
            float4 xv = *(const float4*)&pv[j0];
            a += wv.x * xv.x + wv.y * xv.y + wv.z * xv.z + wv.w * xv.w;
        }
#pragma unroll
        for (int off = 16; off; off >>= 1) a += __shfl_down_sync(0xffffffffu, a, off);
        if (lane == 0) h1[oo] = fmaxf(a + ph1_b[oo], 0.f);
    }
    // g1 = relu(ls1_w @ pv + b)   (256 x 8320)
    for (int oo = warp; oo < 256; oo += 8) {
        float a = 0.f;
        const float* wr = ls1_w + (long long)oo * 8320;
#pragma unroll 4
        for (int jb = 0; jb < 65; ++jb) {
            int j0 = jb * 128 + lane * 4;
            float4 wv = *(const float4*)&wr[j0];
            float4 xv = *(const float4*)&pv[j0];
            a += wv.x * xv.x + wv.y * xv.y + wv.z * xv.z + wv.w * xv.w;
        }
#pragma unroll
        for (int off = 16; off; off >>= 1) a += __shfl_down_sync(0xffffffffu, a, off);
        if (lane == 0) g1v[oo] = fmaxf(a + ls1_b[oo], 0.f);
    }
    __syncthreads();

    // h2 = relu(ph2_w @ h1 + b)   (256 x 512)
    for (int oo = warp; oo < 256; oo += 8) {
        float a = 0.f;
        const float* wr = ph2_w + (long long)oo * 512;
#pragma unroll
        for (int jb = 0; jb < 4; ++jb) {
            int j0 = jb * 128 + lane * 4;
            float4 wv = *(const float4*)&wr[j0];
            float4 xv = *(const float4*)&h1[j0];
            a += wv.x * xv.x + wv.y * xv.y + wv.z * xv.z + wv.w * xv.w;
        }
#pragma unroll
        for (int off = 16; off; off >>= 1) a += __shfl_down_sync(0xffffffffu, a, off);
        if (lane == 0) h2[oo] = fmaxf(a + ph2_b[oo], 0.f);
    }
    __syncthreads();

    // heads: patch_mean = sigmoid(ph3_w @ h2); log_std = clip(ls2_w @ g1)
    if (tid < 12) {
        float a = ph3_b[tid];
        const float* wr = ph3_w + tid * 256;
        for (int j = 0; j < 256; j++) a += wr[j] * h2[j];
        s_pm[tid] = 1.f / (1.f + expf(-a));
    } else if (tid < 24) {
        int t = tid - 12;
        float a = ls2_b[t];
        const float* wr = ls2_w + t * 256;
        for (int j = 0; j < 256; j++) a += wr[j] * g1v[j];
        s_ls[t] = fminf(fmaxf(a, -5.f), 0.f);
    }
    __syncthreads();

    // patches + log_probs
    if (tid < 12) {
        int j = tid & 3;
        float ls  = s_ls[tid];
        float std = expf(ls);
        float pa  = s_pm[tid] + noise[b * 12 + tid] * std;
        float pc  = fminf(fmaxf(pa, 0.f), 1.f);
        float fin = (j < 2) ? pc : fmaf(pc, 0.2f, 0.1f);
        s_fin[tid] = fin;
        if (out_size >= 720) out[528 + b * 12 + tid] = fin;
    }
    if (tid < 3 && out_size >= 720) {
        float lp = 0.f;
#pragma unroll
        for (int j = 0; j < 4; j++) {
            float n = noise[b * 12 + tid * 4 + j];
            lp += n * n + 2.f * s_ls[tid * 4 + j];
        }
        out[480 + b * 3 + tid] = -0.5f * lp;
    }
    __syncthreads();

    // coords: (K*P, 2) = 30 values per batch
    if (tid < 30) {
        int kp = tid >> 1, c = tid & 1;
        int k = kp / 5, p = kp - k * 5;
        float uu  = u[((b * 3 + k) * 5 + p) * 2 + c];
        float ctr = s_fin[k * 4 + c];
        float sz  = s_fin[k * 4 + 2 + c];
        float pt  = (ctr + (uu - 0.5f) * sz) * 256.f;
        pt = fminf(fmaxf(pt, 0.f), 255.f);
        out[b * 30 + tid] = pt;
    }
}

// ---------------------------------------------------------------------------
extern "C" void kernel_launch(void* const* d_in, const int* in_sizes, int n_in,
                              void* d_out, int out_size)
{
    const float* img      = (const float*)d_in[0];
    const float* clinical = (const float*)d_in[1];
    const float* noise    = (const float*)d_in[2];
    const float* u        = (const float*)d_in[3];
    const float* conv1_w  = (const float*)d_in[4];
    const float* conv1_b  = (const float*)d_in[5];
    const float* bn1_g    = (const float*)d_in[6];
    const float* bn1_b    = (const float*)d_in[7];
    const float* bn1_m    = (const float*)d_in[8];
    const float* bn1_v    = (const float*)d_in[9];
    const float* conv2_w  = (const float*)d_in[10];
    const float* conv2_b  = (const float*)d_in[11];
    const float* bn2_g    = (const float*)d_in[12];
    const float* bn2_b    = (const float*)d_in[13];
    const float* bn2_m    = (const float*)d_in[14];
    const float* bn2_v    = (const float*)d_in[15];
    const float* clin_w   = (const float*)d_in[16];
    const float* clin_b   = (const float*)d_in[17];
    const float* ph1_w    = (const float*)d_in[18];
    const float* ph1_b    = (const float*)d_in[19];
    const float* ph2_w    = (const float*)d_in[20];
    const float* ph2_b    = (const float*)d_in[21];
    const float* ph3_w    = (const float*)d_in[22];
    const float* ph3_b    = (const float*)d_in[23];
    const float* ls1_w    = (const float*)d_in[24];
    const float* ls1_b    = (const float*)d_in[25];
    const float* ls2_w    = (const float*)d_in[26];
    const float* ls2_b    = (const float*)d_in[27];
    float* out = (float*)d_out;

    float* x1 = nullptr;
    float* pooled = nullptr;
    cudaGetSymbolAddress((void**)&x1, g_x1);
    cudaGetSymbolAddress((void**)&pooled, g_pooled);

    dim3 grid(16, 8, 16);
    conv_bn_relu_kernel<256, false><<<grid, 256>>>(
        img, conv1_w, conv1_b, bn1_g, bn1_b, bn1_m, bn1_v, x1);
    conv_bn_relu_kernel<512, true><<<grid, 256>>>(
        x1, conv2_w, conv2_b, bn2_g, bn2_b, bn2_m, bn2_v, pooled);
    tail_kernel<<<16, 256>>>(clinical, noise, u,
                             clin_w, clin_b, ph1_w, ph1_b, ph2_w, ph2_b,
                             ph3_w, ph3_b, ls1_w, ls1_b, ls2_w, ls2_b,
                             out, out_size);
}